// round 6
// baseline (speedup 1.0000x reference)
#include <cuda_runtime.h>
#include <cuda_bf16.h>
#include <math.h>

// Problem constants
#define NSAMP 512
#define L 64
#define C1 32          // conv1 out channels
#define NOUT 25        // 3*8+1 conv2 out channels
#define NB 8           // bins
#define RB 8           // rows per block
#define NRB (L / RB)   // 8 row-blocks

#define TWO_PI_F  6.28318530717958647692f
#define INV_2PI_F 0.15915494309189533577f

// Partial logJ per (sample, rowblock)
__device__ float g_lj_partial[NSAMP * NRB];

typedef unsigned long long ull;

__device__ __forceinline__ ull pack2(float lo, float hi) {
    ull r; asm("mov.b64 %0, {%1, %2};" : "=l"(r) : "f"(lo), "f"(hi)); return r;
}
__device__ __forceinline__ void unpack2(ull v, float& lo, float& hi) {
    asm("mov.b64 {%0, %1}, %2;" : "=f"(lo), "=f"(hi) : "l"(v));
}
__device__ __forceinline__ void fma2(ull& d, ull a, ull b) {
    // packed f32x2 fma: d = a*b + d (two independent fma.rn)
    asm("fma.rn.f32x2 %0, %1, %2, %0;" : "+l"(d) : "l"(a), "l"(b));
}

__device__ __forceinline__ float mod2pi(float v) {
    // matches jnp.remainder (floor-based), result in [0, 2pi)
    return v - floorf(v * INV_2PI_F) * TWO_PI_F;
}

__device__ __forceinline__ float gelu_t(float v) {
    // tanh-approx gelu; tanh(u) = 1 - 2/(exp(2u)+1)
    float u = 0.7978845608028654f * (v + 0.044715f * v * v * v);
    float e = __expf(2.f * u);
    float th = 1.f - __fdividef(2.f, e + 1.f);
    return 0.5f * v * (1.f + th);
}

// ---------------------------------------------------------------------------
// Fused kernel: conv1 (10 h1 rows into smem) -> conv2 at ACTIVE sites
// ((r+2c)%3==0, i.e. c ≡ r mod 3) -> rational-quadratic spline epilogue.
// grid (NRB, NSAMP), block 640.  f32x2 packed FMA throughout the convs.
// ---------------------------------------------------------------------------
#define IC_ST  81                       // odd -> conflict-free conv1 writes
#define ROWSTR (C1 * IC_ST + 8)         // 2600; 2600 % 32 = 8
#define NH1R   (RB + 2)                 // 10 h1 rows
#define SH1_F  (NH1R * ROWSTR)          // 26000
#define SW2_F  (NOUT * C1 * 12)         // 9600 (padded [oc][ic][dr][4])
#define SW1_F  (C1 * 2 * 9)             // 576
#define SIN_W  72
#define SIN_F  (2 * 12 * SIN_W)         // 1728
#define SNO_F  (RB * 22 * NOUT)         // 4400 per quarter
#define SMEM_FLOATS (SH1_F + SW2_F + 32 + SW1_F + 32 + SIN_F + 4 * SNO_F + 32)

__global__ __launch_bounds__(640, 1)
void k_fused(const float* __restrict__ x, const float* __restrict__ mfz,
             const float* __restrict__ w1, const float* __restrict__ b1,
             const float* __restrict__ w2, const float* __restrict__ b2,
             float* __restrict__ fx_out)
{
    extern __shared__ float sm[];
    float* sh1  = sm;                   // [10 rows][32 ic][81]: col c at ic*81 + c + 4
    float* sw2  = sh1 + SH1_F;          // padded: [(oc*32+ic)*12 + dr*4 + t]
    float* sb2  = sw2 + SW2_F;
    float* sw1  = sb2 + 32;
    float* sb1  = sw1 + SW1_F;
    float* s_in = sb1 + 32;             // [2 ch][12 rows][72]: col c at idx c+4
    float* sno  = s_in + SIN_F;         // 4 x [row][p(0..21)][25]
    float* sred = sno + 4 * SNO_F;

    const int s   = blockIdx.y;
    const int rb  = blockIdx.x;
    const int tid = threadIdx.x;
    const float* xs = x + (size_t)s * L * L;

    // ---- phase 0: weights (w2 repacked padded), passive copy, sincos tile ----
    for (int i = tid; i < NOUT * C1 * 9; i += 640) {
        int oc   = i / 288;
        int r288 = i - oc * 288;
        int ic   = r288 / 9;
        int t9   = r288 - ic * 9;
        int dr   = t9 / 3;
        int t    = t9 - dr * 3;
        sw2[(oc * 32 + ic) * 12 + dr * 4 + t] = w2[i];
    }
    if (tid < NOUT) sb2[tid] = b2[tid];
    for (int i = tid; i < SW1_F; i += 640) sw1[i] = w1[i];
    if (tid >= 64 && tid < 64 + C1) sb1[tid - 64] = b1[tid - 64];

    // passive/frozen sites: fx = x
    {
        const size_t base = ((size_t)s * L + rb * RB) * L;
        for (int idx = tid; idx < RB * L; idx += 640) {
            int r = idx >> 6, c = idx & (L - 1);
            int grow = rb * RB + r;
            if (((grow + 2 * c) % 3) != 0)
                fx_out[base + r * L + c] = xs[(rb * RB + r) * L + c];
        }
    }

    // input tile for conv1: global rows rb*8-2 .. rb*8+9 (12), cols -1..64
    for (int i = tid; i < 12 * 66; i += 640) {
        int r = i / 66, pos = i % 66;            // pos <-> col pos-1
        int gr = (rb * RB + r - 2) & (L - 1);
        int gc = (pos - 1) & (L - 1);
        float xv = xs[gr * L + gc];
        float m  = mfz[gr * L + gc];
        float sn, cs;
        __sincosf(xv, &sn, &cs);
        s_in[(0 * 12 + r) * SIN_W + pos + 3] = m * cs;
        s_in[(1 * 12 + r) * SIN_W + pos + 3] = m * sn;
    }
    __syncthreads();

    // ---- phase 1: conv1 + gelu -> sh1, f32x2 over col pairs (c, c+8) ----
    for (int u = tid; u < NH1R * C1 * 4; u += 640) {
        const int oc1 = u & 31;
        const int rr  = (u >> 5) % NH1R;
        const int q4  = u / (NH1R * C1);       // col quarter 0..3
        ull acc2[8];
        {
            float b = sb1[oc1];
            ull bb = pack2(b, b);
            #pragma unroll
            for (int c = 0; c < 8; c++) acc2[c] = bb;
        }
        #pragma unroll
        for (int ch = 0; ch < 2; ch++)
            #pragma unroll
            for (int dr = 0; dr < 3; dr++) {
                const float* rp = s_in + ((ch * 12) + rr + dr) * SIN_W + q4 * 16;
                float a[18];
                a[0] = rp[3];
                #pragma unroll
                for (int v = 0; v < 4; v++) {
                    float4 f4 = *(const float4*)(rp + 4 + v * 4);
                    a[1 + v * 4] = f4.x; a[2 + v * 4] = f4.y;
                    a[3 + v * 4] = f4.z; a[4 + v * 4] = f4.w;
                }
                a[17] = rp[20];
                ull p[10];
                #pragma unroll
                for (int j = 0; j < 10; j++) p[j] = pack2(a[j], a[j + 8]);
                const float* wp = sw1 + oc1 * 18 + ch * 9 + dr * 3;
                ull w0 = pack2(wp[0], wp[0]);
                ull w1v = pack2(wp[1], wp[1]);
                ull w2v = pack2(wp[2], wp[2]);
                #pragma unroll
                for (int c = 0; c < 8; c++) {
                    fma2(acc2[c], p[c],     w0);
                    fma2(acc2[c], p[c + 1], w1v);
                    fma2(acc2[c], p[c + 2], w2v);
                }
            }
        float* rowb = sh1 + rr * ROWSTR + oc1 * IC_ST;
        #pragma unroll
        for (int c = 0; c < 8; c++) {
            float lo, hi;
            unpack2(acc2[c], lo, hi);
            int col0 = q4 * 16 + c;
            int col1 = col0 + 8;
            float g0 = gelu_t(lo), g1 = gelu_t(hi);
            rowb[4 + col0] = g0;
            rowb[4 + col1] = g1;
            if (col0 == 0)  rowb[68] = g0;   // halo: col 64 = col 0
            if (col1 == 63) rowb[3]  = g1;   // halo: col -1 = col 63
        }
    }
    __syncthreads();

    // ---- phase 2: conv2 at active sites, 5 oc x 6 sites (3 f32x2 pairs),
    //      split-K/4 over ic; w loads via single LDS.128 ----
    {
        const int w    = tid >> 5;           // 20 warps
        const int g    = w % 5;              // oc group (uniform per warp)
        const int q    = w / 5;              // ic quarter (uniform per warp)
        const int lane = tid & 31;
        const int row  = lane >> 2;          // 0..7
        const int sub  = lane & 3;           // 0..3 -> sites p = 6*sub..6*sub+5
        const int grow = rb * RB + row;
        const int c0   = grow % 3;
        const int cb   = c0 + 18 * sub;      // col of first site
        const int icb  = q * 8;

        ull acc2[5][3];
        #pragma unroll
        for (int o = 0; o < 5; o++) {
            float b = (q == 0) ? sb2[g * 5 + o] : 0.f;
            ull bb = pack2(b, b);
            acc2[o][0] = bb; acc2[o][1] = bb; acc2[o][2] = bb;
        }

        #pragma unroll
        for (int dr = 0; dr < 3; dr++) {
            const float* hb = sh1 + (row + dr) * ROWSTR + icb * IC_ST + (cb + 3);
            const float* wq = sw2 + (g * 5 * 32 + icb) * 12 + dr * 4;
            #pragma unroll 2
            for (int ic = 0; ic < 8; ic++) {
                const float* hp = hb + ic * IC_ST;
                float a[18];
                #pragma unroll
                for (int j = 0; j < 18; j++) a[j] = hp[j];
                ull ap[9];
                #pragma unroll
                for (int j = 0; j < 3; j++) {
                    ap[3 * j + 0] = pack2(a[6 * j + 0], a[6 * j + 3]);
                    ap[3 * j + 1] = pack2(a[6 * j + 1], a[6 * j + 4]);
                    ap[3 * j + 2] = pack2(a[6 * j + 2], a[6 * j + 5]);
                }
                const float* wic = wq + ic * 12;
                #pragma unroll
                for (int o = 0; o < 5; o++) {
                    float4 w4 = *(const float4*)(wic + o * 384);
                    ull w0 = pack2(w4.x, w4.x);
                    ull w1v = pack2(w4.y, w4.y);
                    ull w2v = pack2(w4.z, w4.z);
                    #pragma unroll
                    for (int j = 0; j < 3; j++) {
                        fma2(acc2[o][j], ap[3 * j + 0], w0);
                        fma2(acc2[o][j], ap[3 * j + 1], w1v);
                        fma2(acc2[o][j], ap[3 * j + 2], w2v);
                    }
                }
            }
        }

        float* outbuf = sno + q * SNO_F;
        #pragma unroll
        for (int j = 0; j < 3; j++) {
            int p0   = 6 * sub + 2 * j;
            int col0 = cb + 6 * j;            // site 2j
            int col1 = col0 + 3;              // site 2j+1
            #pragma unroll
            for (int o = 0; o < 5; o++) {
                float lo, hi;
                unpack2(acc2[o][j], lo, hi);
                if (p0 < 22 && col0 < L)
                    outbuf[(row * 22 + p0) * NOUT + g * 5 + o] = lo;
                if (p0 + 1 < 22 && col1 < L)
                    outbuf[(row * 22 + p0 + 1) * NOUT + g * 5 + o] = hi;
            }
        }
    }
    __syncthreads();

    // ---- phase 3: spline epilogue, one active site per thread ----
    float ljsum = 0.f;
    if (tid < RB * 22) {
        int erow = tid / 22;
        int p    = tid - erow * 22;
        int eg   = rb * RB + erow;
        int ec0  = eg % 3;
        int col  = ec0 + 3 * p;
        if (col < L) {
            float no[NOUT];
            #pragma unroll
            for (int i = 0; i < NOUT; i++)
                no[i] = sno[tid * NOUT + i] + sno[SNO_F + tid * NOUT + i]
                      + sno[2 * SNO_F + tid * NOUT + i] + sno[3 * SNO_F + tid * NOUT + i];

            // softmax -> circular knots, fully in registers
            float kxc[NB + 1], kyc[NB + 1], sd[NB + 1];
            {
                float mx = no[0];
                #pragma unroll
                for (int i = 1; i < NB; i++) mx = fmaxf(mx, no[i]);
                float e[NB], S = 0.f;
                #pragma unroll
                for (int i = 0; i < NB; i++) { e[i] = __expf(no[i] - mx); S += e[i]; }
                float inv = __fdividef(TWO_PI_F, S);
                kxc[0] = 0.f; float cum = 0.f;
                #pragma unroll
                for (int i = 0; i < NB; i++) { cum += e[i]; kxc[i + 1] = cum * inv; }
            }
            {
                float mx = no[NB];
                #pragma unroll
                for (int i = 1; i < NB; i++) mx = fmaxf(mx, no[NB + i]);
                float e[NB], S = 0.f;
                #pragma unroll
                for (int i = 0; i < NB; i++) { e[i] = __expf(no[NB + i] - mx); S += e[i]; }
                float inv = __fdividef(TWO_PI_F, S);
                kyc[0] = 0.f; float cum = 0.f;
                #pragma unroll
                for (int i = 0; i < NB; i++) { cum += e[i]; kyc[i + 1] = cum * inv; }
            }
            #pragma unroll
            for (int i = 0; i < NB; i++) {
                float v = no[2 * NB + i];
                sd[i] = fmaxf(v, 0.f) + __logf(1.f + __expf(-fabsf(v)));
            }
            sd[NB] = sd[0];
            float tpar = no[3 * NB];

            float xv = xs[eg * L + col];
            float x1 = mod2pi(xv);          // mask_active = 1 here

            // bin select via unrolled compare chain
            float kxk = kxc[0], kxk1 = kxc[1];
            float kyk = kyc[0], kyk1 = kyc[1];
            float sk  = sd[0],  sk1  = sd[1];
            #pragma unroll
            for (int m = 1; m < NB; m++) {
                if (x1 >= kxc[m]) {
                    kxk = kxc[m]; kxk1 = kxc[m + 1];
                    kyk = kyc[m]; kyk1 = kyc[m + 1];
                    sk  = sd[m];  sk1  = sd[m + 1];
                }
            }

            float wk = kxk1 - kxk, hk = kyk1 - kyk;
            float slope = __fdividef(hk, wk);
            float xi = __saturatef(__fdividef(x1 - kxk, wk));
            float om = 1.f - xi;
            float den = slope + (sk1 + sk - 2.f * slope) * xi * om;
            float y   = kyk + hk * __fdividef(slope * xi * xi + sk * xi * om, den);
            float lnum = slope * slope * (sk1 * xi * xi + 2.f * slope * xi * om + sk * om * om);
            ljsum = __logf(lnum) - 2.f * __logf(den);
            float fx1 = y + tpar;
            fx_out[((size_t)s * L + eg) * L + col] = mod2pi(fx1);
        }
    }

    // block reduction of ljsum (20 warps)
    #pragma unroll
    for (int off = 16; off; off >>= 1)
        ljsum += __shfl_down_sync(0xffffffffu, ljsum, off);
    if ((tid & 31) == 0) sred[tid >> 5] = ljsum;
    __syncthreads();
    if (tid == 0) {
        float tot = 0.f;
        #pragma unroll
        for (int w = 0; w < 20; w++) tot += sred[w];
        g_lj_partial[s * NRB + rb] = tot;
    }
}

// ---------------------------------------------------------------------------
// Kernel C: logJ[s] = sum over rowblock partials (deterministic)
// ---------------------------------------------------------------------------
__global__ void k_lj(float* __restrict__ lj_out)
{
    int s = blockIdx.x * blockDim.x + threadIdx.x;
    if (s < NSAMP) {
        float t = 0.f;
        #pragma unroll
        for (int i = 0; i < NRB; i++) t += g_lj_partial[s * NRB + i];
        lj_out[s] = t;
    }
}

// ---------------------------------------------------------------------------
// Launch
// inputs: x, mask_active, mask_passive, mask_frozen, conv1_w, conv1_b, conv2_w, conv2_b
// output: fx (512*64*64 floats) followed by logJ (512 floats)
// ---------------------------------------------------------------------------
extern "C" void kernel_launch(void* const* d_in, const int* in_sizes, int n_in,
                              void* d_out, int out_size)
{
    const float* x   = (const float*)d_in[0];
    const float* mfz = (const float*)d_in[3];
    const float* w1  = (const float*)d_in[4];
    const float* b1  = (const float*)d_in[5];
    const float* w2  = (const float*)d_in[6];
    const float* b2  = (const float*)d_in[7];
    float* fx = (float*)d_out;
    float* lj = fx + (size_t)NSAMP * L * L;

    static_assert(SMEM_FLOATS * 4 < 227 * 1024, "smem too big");
    cudaFuncSetAttribute(k_fused,
                         cudaFuncAttributeMaxDynamicSharedMemorySize,
                         SMEM_FLOATS * 4);

    dim3 grid(NRB, NSAMP);
    k_fused<<<grid, 640, SMEM_FLOATS * 4>>>(x, mfz, w1, b1, w2, b2, fx);
    k_lj<<<(NSAMP + 255) / 256, 256>>>(lj);
}